// round 2
// baseline (speedup 1.0000x reference)
#include <cuda_runtime.h>
#include <cuda_bf16.h>

#define CC      2048
#define HW      49
#define SIDE    7
#define CGROUPS 8
#define NTHR    512
#define SPLIT   8
#define CPS     (CC / SPLIT)      // 256 channels per CTA
#define NMAX    256

// scratch: [n][split][p][5]
__device__ float g_scratch[NMAX * SPLIT * HW * 5];

__global__ __launch_bounds__(NTHR, 3)
void rpcp_partial_kernel(const float* __restrict__ x,
                         const float* __restrict__ Wlin,
                         float* __restrict__ scratch)
{
    __shared__ float4 wsh[CPS];                 // weight slice for this CTA's channels
    __shared__ float  acc[CGROUPS][HW][5];

    const int tid = threadIdx.x;
    const int n   = blockIdx.x >> 3;            // SPLIT = 8
    const int sp  = blockIdx.x & (SPLIT - 1);
    const int c0  = sp * CPS;

    // pack weights for our 256-channel slice: {W1_0, W1_1, W2_0, W2_1}
    for (int c = tid; c < CPS; c += NTHR) {
        const int cc = c0 + c;
        wsh[c] = make_float4(Wlin[cc],              // W1_0
                             Wlin[2 * CC + cc],     // W1_1
                             Wlin[CC + cc],         // W2_0
                             Wlin[3 * CC + cc]);    // W2_1
    }
    __syncthreads();

    const int p  = tid & 63;
    const int cg = tid >> 6;

    float s = 0.f, a0 = 0.f, a1 = 0.f, d0 = 0.f, d1 = 0.f;
    if (p < HW) {
        const float* xp = x + (size_t)n * CC * HW + (size_t)c0 * HW + p;
        #pragma unroll 8
        for (int c = cg; c < CPS; c += CGROUPS) {
            float  v = __ldg(xp + c * HW);          // coalesced across lanes
            float4 w = wsh[c];
            s  += v;
            a0 = fmaf(v, w.x, a0);
            a1 = fmaf(v, w.y, a1);
            d0 = fmaf(v, w.z, d0);
            d1 = fmaf(v, w.w, d1);
        }
        acc[cg][p][0] = s;  acc[cg][p][1] = a0; acc[cg][p][2] = a1;
        acc[cg][p][3] = d0; acc[cg][p][4] = d1;
    }
    __syncthreads();

    if (tid < HW * 5) {
        const int pp = tid / 5, k = tid % 5;
        float t = 0.f;
        #pragma unroll
        for (int g = 0; g < CGROUPS; g++) t += acc[g][pp][k];
        scratch[((n * SPLIT + sp) * HW + pp) * 5 + k] = t;
    }
}

__global__ __launch_bounds__(256, 4)
void rpcp_final_kernel(const float* __restrict__ scratch,
                       const float* __restrict__ bias,
                       float* __restrict__ out)
{
    __shared__ float fin[HW][5];   // {sum, a0, a1, d0, d1}
    __shared__ float gaps[HW];
    __shared__ float dls[HW];
    __shared__ int   s_idx;
    __shared__ float s_gmean;

    const int n   = blockIdx.x;
    const int tid = threadIdx.x;

    if (tid < HW * 5) {
        const int pp = tid / 5, k = tid % 5;
        float t = 0.f;
        #pragma unroll
        for (int sp = 0; sp < SPLIT; sp++)
            t += scratch[((n * SPLIT + sp) * HW + pp) * 5 + k];
        fin[pp][k] = t;
    }
    __syncthreads();

    // argmax over channel-sum (first occurrence on ties)
    if (tid == 0) {
        int best = 0; float bv = fin[0][0];
        #pragma unroll
        for (int q = 1; q < HW; q++) {
            float v = fin[q][0];
            if (v > bv) { bv = v; best = q; }
        }
        s_idx = best;
    }
    __syncthreads();
    const int idx = s_idx;

    if (tid < HW) {
        const float A0 = fin[idx][1];
        const float A1 = fin[idx][2];
        float pr0 = fin[tid][3] + A0 + bias[0];
        float pr1 = fin[tid][4] + A1 + bias[1];
        pr0 = fmaxf(pr0, 0.f);
        pr1 = fmaxf(pr1, 0.f);
        if (tid == idx) { pr0 = 0.f; pr1 = 0.f; }

        const float ri = (float)(tid / SIDE - idx / SIDE) * (1.f / (float)SIDE);
        const float rj = (float)(tid % SIDE - idx % SIDE) * (1.f / (float)SIDE);
        const float rd = sqrtf(ri * ri + rj * rj);
        const float ang = (atan2f(rj, ri) * (1.f / 3.14159265358979323846f) + 1.f) * 0.5f;

        float dl = pr0 - rd; dl *= dl;
        float g  = pr1 - ang;
        if (g < 0.f) g += 1.f;
        gaps[tid] = g;
        dls[tid]  = dl;
    }
    __syncthreads();

    if (tid == 0) {
        float t = 0.f;
        #pragma unroll
        for (int q = 0; q < HW; q++) t += gaps[q];
        s_gmean = t * (1.f / (float)HW);
    }
    __syncthreads();

    if (tid < HW) {
        float g = gaps[tid] - s_gmean;
        out[n * HW + tid] = dls[tid] + g * g;
    }
}

extern "C" void kernel_launch(void* const* d_in, const int* in_sizes, int n_in,
                              void* d_out, int out_size)
{
    const float* x    = (const float*)d_in[0];
    const float* Wlin = (const float*)d_in[1];
    const float* b    = (const float*)d_in[2];
    float*       out  = (float*)d_out;

    const int N = in_sizes[0] / (CC * HW);   // 256

    float* scratch = nullptr;
    cudaGetSymbolAddress((void**)&scratch, g_scratch);

    rpcp_partial_kernel<<<N * SPLIT, NTHR>>>(x, Wlin, scratch);
    rpcp_final_kernel<<<N, 256>>>(scratch, b, out);
}